// round 13
// baseline (speedup 1.0000x reference)
#include <cuda_runtime.h>
#include <cuda_fp16.h>
#include <math_constants.h>
#include <cstdint>

#define NROWS 8192
#define DIM   512
#define BT    128            // block tile (M=N)
#define NCH   4              // k chunks of 128 fp8
#define NB    (NROWS / BT)   // 64
#define NBLK  (NB * (NB + 1) / 2)   // 2080 upper-triangle blocks
#define LDW   36             // padded row stride in b32 units (32 data + 4 pad)
#define STG   (BT * LDW * 4) // 18432 B per stage side
#define SMEM_BYTES (4 * STG) // 73728 B
typedef unsigned long long ull;

// Scratch (device globals: allocation-free)
__device__ float    g_x[NROWS * DIM];          // fp32 weighted features (exact)
__device__ uint32_t g_x8[NROWS * DIM / 4];     // e4m3 x4 packed
__device__ float    g_sq[NROWS];               // ||x||^2 fp32 (exact)
__device__ float    g_sqq[NROWS];              // ||e4m3(x)||^2 (consistent geometry)
__device__ ull      g_negC[(size_t)NROWS * NB]; // per-(row, colblock) min-neg cand
__device__ ull      g_posC[(size_t)NROWS * NB]; // per-(row, colblock) max-pos cand
__device__ float    g_ap2[NROWS];              // exact d2 of refined positive
__device__ float    g_an2[NROWS];              // exact d2 of refined negative
__device__ int      g_tstride;

static __device__ __forceinline__ void cp16(uint32_t s, const void* g) {
    asm volatile("cp.async.cg.shared.global [%0], [%1], 16;" :: "r"(s), "l"(g));
}
static __device__ __forceinline__ uint32_t e4m3x4(float v0, float v1, float v2, float v3) {
    uint16_t lo, hi;
    asm("cvt.rn.satfinite.e4m3x2.f32 %0, %1, %2;" : "=h"(lo) : "f"(v1), "f"(v0));
    asm("cvt.rn.satfinite.e4m3x2.f32 %0, %1, %2;" : "=h"(hi) : "f"(v3), "f"(v2));
    return (uint32_t)lo | ((uint32_t)hi << 16);
}
static __device__ __forceinline__ float2 dq2(uint16_t u) {
    uint32_t h2;
    asm("cvt.rn.f16x2.e4m3x2 %0, %1;" : "=r"(h2) : "h"(u));
    const __half2 h = *reinterpret_cast<const __half2*>(&h2);
    return __half22float2(h);
}
static __device__ __forceinline__ void mma_fp8(float* d, const uint32_t* a, const uint32_t* b) {
    asm volatile(
        "mma.sync.aligned.m16n8k32.row.col.f32.e4m3.e4m3.f32 "
        "{%0,%1,%2,%3}, {%4,%5,%6,%7}, {%8,%9}, {%0,%1,%2,%3};\n"
        : "+f"(d[0]), "+f"(d[1]), "+f"(d[2]), "+f"(d[3])
        : "r"(a[0]), "r"(a[1]), "r"(a[2]), "r"(a[3]), "r"(b[0]), "r"(b[1]));
}
static __device__ __forceinline__ ull packv(float v, int idx) {
    return ((ull)__float_as_uint(v) << 32) | (unsigned)idx;
}

// ---------------------------------------------------------------------------
__global__ void detect_kernel(const int* __restrict__ tw) {
    __shared__ int red[32];
    const int t = threadIdx.x;
    int acc = 0;
    for (int i = t; i < NROWS; i += 1024) acc |= tw[2 * i + 1];
    #pragma unroll
    for (int o = 16; o; o >>= 1) acc |= __shfl_down_sync(0xffffffffu, acc, o);
    if ((t & 31) == 0) red[t >> 5] = acc;
    __syncthreads();
    if (t < 32) {
        int v = red[t];
        #pragma unroll
        for (int o = 16; o; o >>= 1) v |= __shfl_down_sync(0xffffffffu, v, o);
        if (t == 0) g_tstride = (v == 0) ? 2 : 1;
    }
}

__global__ void prep_kernel(const float* __restrict__ in, const float* __restrict__ Aw) {
    const int row = blockIdx.x;
    const int t = threadIdx.x;  // 128
    const float4 a = ((const float4*)(in + (size_t)row * DIM))[t];
    const float4 b = ((const float4*)(Aw + (size_t)row * DIM))[t];
    float4 v;
    v.x = a.x * b.x; v.y = a.y * b.y; v.z = a.z * b.z; v.w = a.w * b.w;
    ((float4*)(g_x + (size_t)row * DIM))[t] = v;

    const uint32_t p = e4m3x4(v.x, v.y, v.z, v.w);
    g_x8[(size_t)row * (DIM / 4) + t] = p;

    float s = v.x * v.x + v.y * v.y + v.z * v.z + v.w * v.w;
    const float2 q0 = dq2((uint16_t)(p & 0xFFFFu));
    const float2 q1 = dq2((uint16_t)(p >> 16));
    float sq8 = q0.x * q0.x + q0.y * q0.y + q1.x * q1.x + q1.y * q1.y;
    #pragma unroll
    for (int o = 16; o; o >>= 1) {
        s   += __shfl_down_sync(0xffffffffu, s, o);
        sq8 += __shfl_down_sync(0xffffffffu, sq8, o);
    }
    __shared__ float red[4], redq[4];
    if ((t & 31) == 0) { red[t >> 5] = s; redq[t >> 5] = sq8; }
    __syncthreads();
    if (t == 0) {
        g_sq[row]  = red[0] + red[1] + red[2] + red[3];
        g_sqq[row] = redq[0] + redq[1] + redq[2] + redq[3];
    }
}

// ---------------------------------------------------------------------------
// fp8 e4m3 mma.sync Gram (selection only) on upper-triangle blocks.
// Per-block candidates written to g_negC/g_posC (no atomics).
// ---------------------------------------------------------------------------
__global__ __launch_bounds__(256, 2) void gram_mma(const int* __restrict__ tw) {
    extern __shared__ uint32_t smem[];
    const uint32_t sb = (uint32_t)__cvta_generic_to_shared(smem);

    const int tid  = threadIdx.x;
    const int lane = tid & 31;
    const int wid  = tid >> 5;
    const int g    = lane >> 2;
    const int c    = lane & 3;
    const int warpM = (wid & 3) * 32;
    const int warpN = (wid >> 2) * 64;
    const int ts = g_tstride;

    // closed-form linear id -> upper triangle (bi <= bj)
    const float fb = (float)blockIdx.x;
    int bi = (int)(64.5f - sqrtf(fmaf(-2.0f, fb, 4160.25f)));
    int rem = blockIdx.x - (bi * (2 * NB - bi + 1)) / 2;
    if (rem < 0) { --bi; rem = blockIdx.x - (bi * (2 * NB - bi + 1)) / 2; }
    else if (rem >= NB - bi) { ++bi; rem = blockIdx.x - (bi * (2 * NB - bi + 1)) / 2; }
    const int bj = bi + rem;
    const int R = bi * BT, C = bj * BT;

    float acc[2][8][4];
    #pragma unroll
    for (int t = 0; t < 2; ++t)
        #pragma unroll
        for (int n = 0; n < 8; ++n)
            #pragma unroll
            for (int e = 0; e < 4; ++e) acc[t][n][e] = 0.f;

    const int lrow = tid >> 3;
    const int lck  = (tid & 7) << 4;
    const char* gA = (const char*)g_x8 + ((size_t)(R + lrow) * 512) + lck;
    const char* gB = (const char*)g_x8 + ((size_t)(C + lrow) * 512) + lck;
    const uint32_t sA = sb + (uint32_t)lrow * 144 + lck;
    const uint32_t sB = sb + 2u * STG + (uint32_t)lrow * 144 + lck;
    const size_t gstep = (size_t)32 * 512;
    const uint32_t sstep = 32 * 144;

    auto load_stage = [&](int kb, int s) {
        const size_t ko = (size_t)kb * 128;
        const uint32_t so = (uint32_t)s * STG;
        #pragma unroll
        for (int i = 0; i < 4; ++i) {
            cp16(sA + so + i * sstep, gA + ko + i * gstep);
            cp16(sB + so + i * sstep, gB + ko + i * gstep);
        }
    };

    load_stage(0, 0);
    asm volatile("cp.async.commit_group;");

    for (int it = 0; it < NCH; ++it) {
        const int s = it & 1;
        if (it + 1 < NCH) load_stage(it + 1, (it + 1) & 1);
        asm volatile("cp.async.commit_group;");
        asm volatile("cp.async.wait_group 1;");
        __syncthreads();

        const uint32_t* As = smem + (size_t)s * (STG / 4);
        const uint32_t* Bs = smem + 2 * (STG / 4) + (size_t)s * (STG / 4);
        #pragma unroll
        for (int kk = 0; kk < 4; ++kk) {
            const int kb = kk * 8;
            uint32_t af[2][4], bf[8][2];
            #pragma unroll
            for (int t = 0; t < 2; ++t) {
                const int r0 = warpM + t * 16 + g;
                af[t][0] = As[r0 * LDW + kb + c];
                af[t][1] = As[(r0 + 8) * LDW + kb + c];
                af[t][2] = As[r0 * LDW + kb + c + 4];
                af[t][3] = As[(r0 + 8) * LDW + kb + c + 4];
            }
            #pragma unroll
            for (int n = 0; n < 8; ++n) {
                const int nr = warpN + n * 8 + g;
                bf[n][0] = Bs[nr * LDW + kb + c];
                bf[n][1] = Bs[nr * LDW + kb + c + 4];
            }
            #pragma unroll
            for (int t = 0; t < 2; ++t)
                #pragma unroll
                for (int n = 0; n < 8; ++n)
                    mma_fp8(acc[t][n], af[t], bf[n]);
        }
        __syncthreads();
    }

    // ---- epilogue: symmetric hard mining, per-block candidate output ----
    float scj[16]; int tcj[16];
    #pragma unroll
    for (int n = 0; n < 8; ++n) {
        const int j0 = C + warpN + n * 8 + 2 * c;
        scj[2*n]   = g_sqq[j0];    scj[2*n+1] = g_sqq[j0 + 1];
        tcj[2*n]   = tw[ts * j0];  tcj[2*n+1] = tw[ts * (j0 + 1)];
    }
    float sqr4[4]; int tr4[4]; int rowi[4];
    #pragma unroll
    for (int t = 0; t < 2; ++t)
        #pragma unroll
        for (int p = 0; p < 2; ++p) {
            const int ri = R + warpM + t * 16 + p * 8 + g;
            rowi[t*2+p] = ri; sqr4[t*2+p] = g_sqq[ri]; tr4[t*2+p] = tw[ts * ri];
        }

    ull apr[4], anr[4], apc[16], anc[16];
    #pragma unroll
    for (int i = 0; i < 4; ++i)  { apr[i] = packv(0.0f, rowi[i]); anr[i] = 0xFFFFFFFFFFFFFFFFull; }
    #pragma unroll
    for (int n = 0; n < 8; ++n)
        #pragma unroll
        for (int e = 0; e < 2; ++e) {
            const int cj = n * 2 + e;
            apc[cj] = packv(0.0f, C + warpN + n * 8 + 2 * c + e);
            anc[cj] = 0xFFFFFFFFFFFFFFFFull;
        }

    #pragma unroll
    for (int t = 0; t < 2; ++t)
        #pragma unroll
        for (int n = 0; n < 8; ++n)
            #pragma unroll
            for (int p = 0; p < 2; ++p) {
                const int ri = t * 2 + p;
                #pragma unroll
                for (int e = 0; e < 2; ++e) {
                    const int cj = n * 2 + e;
                    const int jg = C + warpN + n * 8 + 2 * c + e;
                    const float d2 = fmaxf(fmaf(-2.f, acc[t][n][p * 2 + e], sqr4[ri] + scj[cj]), 0.f);
                    const ull pr = packv(d2, jg);
                    const ull pc = packv(d2, rowi[ri]);
                    if (tr4[ri] == tcj[cj]) {
                        if (pr > apr[ri]) apr[ri] = pr;
                        if (pc > apc[cj]) apc[cj] = pc;
                    } else {
                        if (pr < anr[ri]) anr[ri] = pr;
                        if (pc < anc[cj]) anc[cj] = pc;
                    }
                }
            }

    // warp-level reductions
    #pragma unroll
    for (int i = 0; i < 4; ++i) {
        #pragma unroll
        for (int m = 1; m <= 2; m <<= 1) {
            ull o;
            o = __shfl_xor_sync(0xffffffffu, apr[i], m); if (o > apr[i]) apr[i] = o;
            o = __shfl_xor_sync(0xffffffffu, anr[i], m); if (o < anr[i]) anr[i] = o;
        }
    }
    #pragma unroll
    for (int i = 0; i < 16; ++i) {
        #pragma unroll
        for (int m = 4; m <= 16; m <<= 1) {
            ull o;
            o = __shfl_xor_sync(0xffffffffu, apc[i], m); if (o > apc[i]) apc[i] = o;
            o = __shfl_xor_sync(0xffffffffu, anc[i], m); if (o < anc[i]) anc[i] = o;
        }
    }

    // block-level combine in (reused) smem, then plain global stores
    ull* s_rap = (ull*)smem;            // [128][2]
    ull* s_ran = s_rap + 256;           // [128][2]
    ull* s_cap = s_ran + 256;           // [128][4]
    ull* s_can = s_cap + 512;           // [128][4]
    const int colgrp = wid >> 2;
    const int mgrp   = wid & 3;

    if (c == 0) {
        #pragma unroll
        for (int i = 0; i < 4; ++i) {
            const int lr = warpM + (i >> 1) * 16 + (i & 1) * 8 + g;
            s_rap[lr * 2 + colgrp] = apr[i];
            s_ran[lr * 2 + colgrp] = anr[i];
        }
    }
    if (g == 0) {
        #pragma unroll
        for (int n = 0; n < 8; ++n)
            #pragma unroll
            for (int e = 0; e < 2; ++e) {
                const int lc = warpN + n * 8 + 2 * c + e;
                s_cap[lc * 4 + mgrp] = apc[n * 2 + e];
                s_can[lc * 4 + mgrp] = anc[n * 2 + e];
            }
    }
    __syncthreads();
    if (tid < 128) {
        ull a0 = s_rap[tid * 2], a1 = s_rap[tid * 2 + 1];
        ull b0 = s_ran[tid * 2], b1 = s_ran[tid * 2 + 1];
        g_posC[(size_t)(R + tid) * NB + bj] = a0 > a1 ? a0 : a1;
        g_negC[(size_t)(R + tid) * NB + bj] = b0 < b1 ? b0 : b1;
        if (bi != bj) {
            ull ca = s_cap[tid * 4], cn = s_can[tid * 4];
            #pragma unroll
            for (int q = 1; q < 4; ++q) {
                const ull ua = s_cap[tid * 4 + q], un = s_can[tid * 4 + q];
                if (ua > ca) ca = ua;
                if (un < cn) cn = un;
            }
            g_posC[(size_t)(C + tid) * NB + bi] = ca;
            g_negC[(size_t)(C + tid) * NB + bi] = cn;
        }
    }
}

// ---------------------------------------------------------------------------
// Refine: top-4 negative / top-2 positive block candidates, exact fp32 d2.
// One warp per row.
// ---------------------------------------------------------------------------
__global__ __launch_bounds__(256) void refine_kernel() {
    const int wid  = threadIdx.x >> 5;
    const int lane = threadIdx.x & 31;
    const int row  = blockIdx.x * 8 + wid;

    const ull* neg = &g_negC[(size_t)row * NB];
    const ull* pos = &g_posC[(size_t)row * NB];
    const float sqi = g_sq[row];
    const float4* xi = (const float4*)(g_x + (size_t)row * DIM);
    float4 xv[4];
    #pragma unroll
    for (int q = 0; q < 4; ++q) xv[q] = xi[q * 32 + lane];

    auto exact_d2 = [&](int j) -> float {
        const float4* xj = (const float4*)(g_x + (size_t)j * DIM);
        float dot = 0.f;
        #pragma unroll
        for (int q = 0; q < 4; ++q) {
            const float4 b = xj[q * 32 + lane];
            dot = fmaf(xv[q].x, b.x, fmaf(xv[q].y, b.y, fmaf(xv[q].z, b.z, fmaf(xv[q].w, b.w, dot))));
        }
        #pragma unroll
        for (int o = 16; o; o >>= 1) dot += __shfl_xor_sync(0xffffffffu, dot, o);
        return fmaf(-2.f, dot, sqi + g_sq[j]);
    };

    // negatives: top-4 smallest packed candidates, exact min
    ull c0 = neg[lane], c1 = neg[lane + 32];
    float an = CUDART_INF_F;
    #pragma unroll
    for (int k = 0; k < 4; ++k) {
        ull m = c0 < c1 ? c0 : c1;
        #pragma unroll
        for (int o = 16; o; o >>= 1) {
            const ull v = __shfl_xor_sync(0xffffffffu, m, o);
            if (v < m) m = v;
        }
        if (c0 == m) c0 = 0xFFFFFFFFFFFFFFFFull;
        else if (c1 == m) c1 = 0xFFFFFFFFFFFFFFFFull;
        if (m != 0xFFFFFFFFFFFFFFFFull) {
            const int j = (int)((unsigned)m & 8191u);
            an = fminf(an, exact_d2(j));
        }
    }

    // positives: top-2 largest packed candidates, exact max
    ull p0 = pos[lane], p1 = pos[lane + 32];
    float ap = 0.f;
    #pragma unroll
    for (int k = 0; k < 2; ++k) {
        ull m = p0 > p1 ? p0 : p1;
        #pragma unroll
        for (int o = 16; o; o >>= 1) {
            const ull v = __shfl_xor_sync(0xffffffffu, m, o);
            if (v > m) m = v;
        }
        if (p0 == m) p0 = 0ull;
        else if (p1 == m) p1 = 0ull;
        const int j = (int)((unsigned)m & 8191u);
        ap = fmaxf(ap, exact_d2(j));
    }

    if (lane == 0) {
        g_an2[row] = an;
        g_ap2[row] = ap;
    }
}

// ---------------------------------------------------------------------------
__global__ void loss_kernel(float* __restrict__ out) {
    __shared__ float red[32];
    const int t = threadIdx.x;  // 1024
    float s = 0.f;
    #pragma unroll
    for (int h = 0; h < 2; ++h) {
        const int i = t * 8 + h * 4;
        const float4 ap = *(const float4*)&g_ap2[i];
        const float4 an = *(const float4*)&g_an2[i];
        s += fmaxf(sqrtf(fmaxf(ap.x, 1e-12f)) - sqrtf(fmaxf(an.x, 1e-12f)) + 0.5f, 0.f);
        s += fmaxf(sqrtf(fmaxf(ap.y, 1e-12f)) - sqrtf(fmaxf(an.y, 1e-12f)) + 0.5f, 0.f);
        s += fmaxf(sqrtf(fmaxf(ap.z, 1e-12f)) - sqrtf(fmaxf(an.z, 1e-12f)) + 0.5f, 0.f);
        s += fmaxf(sqrtf(fmaxf(ap.w, 1e-12f)) - sqrtf(fmaxf(an.w, 1e-12f)) + 0.5f, 0.f);
    }
    #pragma unroll
    for (int o = 16; o; o >>= 1) s += __shfl_down_sync(0xffffffffu, s, o);
    if ((t & 31) == 0) red[t >> 5] = s;
    __syncthreads();
    if (t < 32) {
        float v = red[t];
        #pragma unroll
        for (int o = 16; o; o >>= 1) v += __shfl_down_sync(0xffffffffu, v, o);
        if (t == 0) out[0] = v * (1.0f / (float)NROWS);
    }
}

// ---------------------------------------------------------------------------
extern "C" void kernel_launch(void* const* d_in, const int* in_sizes, int n_in,
                              void* d_out, int out_size) {
    const float* inputs = (const float*)d_in[0];
    const float* A      = (const float*)d_in[1];
    const int*   tw     = (const int*)d_in[2];

    cudaFuncSetAttribute(gram_mma, cudaFuncAttributeMaxDynamicSharedMemorySize, SMEM_BYTES);

    detect_kernel<<<1, 1024>>>(tw);
    prep_kernel<<<NROWS, 128>>>(inputs, A);
    gram_mma<<<NBLK, 256, SMEM_BYTES>>>(tw);
    refine_kernel<<<NROWS / 8, 256>>>();
    loss_kernel<<<1, 1024>>>((float*)d_out);
}